// round 12
// baseline (speedup 1.0000x reference)
#include <cuda_runtime.h>
#include <math.h>

// Problem constants
#define BATCH 64
#define SEQ   512
#define HID   1024
#define EMB   256
#define NCHAR 128

// Geometry (R6 winner): 128 persistent CTAs = 4 batch-groups (tb) x 32 j-tiles (tj).
// 256 threads = 8 warps.
#define GRID     128
#define NTHREADS 256
#define BT       16      // batch rows per CTA
#define JT       32      // hidden rows per CTA

#define SH_STRIDE 20     // padded h-tile row stride (words)
#define SP_STRIDE 34     // partial row stride (words)

#define SW_FLOATS (HID * JT)                    // 32768
#define SH_FLOATS (HID * SH_STRIDE)             // 20480
#define SP_FLOATS (4 * 16 * SP_STRIDE)          // 2176
#define SMEM_FLOATS (SW_FLOATS + SH_FLOATS + SP_FLOATS)
#define SMEM_BYTES  (SMEM_FLOATS * 4)           // 221,696 B

typedef unsigned long long u64;

// packed f32x2 (sm_100+): one SASS FFMA2 = 2 FMAs
#define FMA2(d, a, b)    asm("fma.rn.f32x2 %0, %1, %2, %0;" : "+l"(d) : "l"(a), "l"(b))
#define PACK2(d, lo, hi) asm("mov.b64 %0, {%1, %2};" : "=l"(d) : "f"(lo), "f"(hi))

// Device-global scratch
__device__ float g_U[NCHAR * HID];                 // U = embeddings @ W_ih^T
__device__ float g_h[2][BATCH * HID];              // ping-pong hidden state
__device__ __align__(128) unsigned g_flag[4][32];  // per-group arrival flags (one 128B line/group)
__device__ unsigned g_epoch[GRID];                 // per-CTA launch epoch (monotonic tags)

// ---------------------------------------------------------------------------
// Flag-array group barrier: each CTA stores its own flag; warp 0 lanes poll
// all 32 flags directly (one coalesced load per iteration). Wait completes one
// L2 latency after the LAST producer's store — no atomic serialization, no
// leader release hop. Wrap-safe >= compare prevents fast-CTA-overwrite
// deadlock (a CTA may already be one phase ahead).
// ---------------------------------------------------------------------------
__device__ __forceinline__ void flag_bar(unsigned* line, int tj, unsigned tag) {
    __syncthreads();                      // all this CTA's global stores issued
    if (threadIdx.x < 32) {
        if (threadIdx.x == 0) {
            __threadfence();              // h writes visible before flag
            asm volatile("st.relaxed.gpu.global.u32 [%0], %1;"
                         :: "l"(line + tj), "r"(tag) : "memory");
        }
        unsigned v;
        do {
            asm volatile("ld.relaxed.gpu.global.u32 %0, [%1];"
                         : "=r"(v) : "l"(line + threadIdx.x) : "memory");
        } while (!__all_sync(0xffffffffu, (int)(v - tag) >= 0));
        __threadfence();                  // acquire: flags observed -> h reads valid
    }
    __syncthreads();
}

// ---------------------------------------------------------------------------
// Kernel 0: U[c][j] = sum_e emb[c][e] * W_ih[j][e]
// ---------------------------------------------------------------------------
__global__ void u_kernel(const float* __restrict__ emb, const float* __restrict__ wih) {
    int gt   = blockIdx.x * blockDim.x + threadIdx.x;
    int warp = gt >> 5;
    int lane = gt & 31;
    int e0   = lane * 8;
    for (int i = 0; i < 32; i++) {
        int o = warp * 32 + i;
        int c = o >> 10;
        int j = o & 1023;
        const float4* ep = (const float4*)(emb + c * EMB + e0);
        const float4* wp = (const float4*)(wih + j * EMB + e0);
        float4 e1 = __ldg(ep),     e2 = __ldg(ep + 1);
        float4 w1 = __ldg(wp),     w2 = __ldg(wp + 1);
        float acc = e1.x*w1.x + e1.y*w1.y + e1.z*w1.z + e1.w*w1.w
                  + e2.x*w2.x + e2.y*w2.y + e2.z*w2.z + e2.w*w2.w;
        acc += __shfl_xor_sync(0xffffffffu, acc, 16);
        acc += __shfl_xor_sync(0xffffffffu, acc, 8);
        acc += __shfl_xor_sync(0xffffffffu, acc, 4);
        acc += __shfl_xor_sync(0xffffffffu, acc, 2);
        acc += __shfl_xor_sync(0xffffffffu, acc, 1);
        if (lane == 0) g_U[c * HID + j] = acc;
    }
}

// ---------------------------------------------------------------------------
// Persistent RNN scan — identical compute to the 4110us winner.
// Warp w: bhalf = w&1 (8 batches), kq = w>>1 (k quarter).
// Lane l:  jg = l&7 (4 j's), ks = l>>3; klane = kq*4+ks; k = kk*16 + klane.
// Per lane per kk: 2x float4 h (batch pairs), 1x float4 W, 4 dup MOVs,
// 16 FFMA2. 64 kk -> 1024 FFMA2/lane.
// ---------------------------------------------------------------------------
__global__ void __launch_bounds__(NTHREADS, 1) rnn_kernel(
    const int*   __restrict__ tids,
    const float* __restrict__ whh,
    const float* __restrict__ h0,
    const float* __restrict__ wproj,
    const float* __restrict__ bproj,
    float*       __restrict__ out)
{
    extern __shared__ float smem[];
    float* sW = smem;                         // [1024][32]   W slice, transposed
    float* sH = smem + SW_FLOATS;             // [1024][20]   h tile, transposed, padded
    float* sP = smem + SW_FLOATS + SH_FLOATS; // [4][16][34]  cross-warp partials

    const int tid = threadIdx.x;
    const int cta = blockIdx.x;
    const int tb  = cta >> 5;      // 0..3 (barrier group)
    const int tj  = cta & 31;      // 0..31
    const int b0  = tb * BT;
    const int j0  = tj * JT;
    unsigned* line = g_flag[tb];

    // per-launch tag base (monotonic across graph replays; 514 phases < 1024)
    __shared__ unsigned s_tagbase;
    if (tid == 0) {
        unsigned e = g_epoch[cta] + 1u;
        g_epoch[cta] = e;
        s_tagbase = e * 1024u;
    }

    // one-time: W_hh slice transposed into SMEM
    for (int idx = tid; idx < JT * HID; idx += NTHREADS) {
        int jj = idx >> 10;
        int k  = idx & 1023;
        sW[k * JT + jj] = whh[(j0 + jj) * HID + k];
    }
    // one-time: init h ping buffer (this CTA's tile)
    for (int idx = tid; idx < BT * JT; idx += NTHREADS) {
        int bb = idx >> 5;
        int jj = idx & 31;
        g_h[0][(b0 + bb) * HID + (j0 + jj)] = h0[j0 + jj];
    }

    flag_bar(line, tj, s_tagbase + 1u);            // phase 1 (init visible)
    const unsigned tagbase = s_tagbase;

    const int w     = tid >> 5;
    const int l     = tid & 31;
    const int bhalf = w & 1;       // 8-batch half
    const int kq    = w >> 1;      // 0..3
    const int jg    = l & 7;       // 4 j's
    const int ks    = l >> 3;      // 0..3
    const int klane = kq * 4 + ks;

    // staging assignment: thread -> (bb, kq8)
    const int st_bb  = tid & 15;
    const int st_kq8 = tid >> 4;   // 0..15

    // combine assignment: thread -> (bpg, jc)
    const int jc  = tid & 31;
    const int bpg = tid >> 5;      // 0..7
    const int cbh = bpg >> 2;
    const int cbp = bpg & 3;
    const int cg  = cbh * 8 + (jc >> 2);
    const int cbase = cbp * 8 + (jc & 3) * 2;
    const int cb0 = b0 + cbh * 8 + cbp * 2;

    const float* hptr0 = sH + klane * SH_STRIDE + bhalf * 8;
    const float* wptr0 = sW + klane * JT + jg * 4;

    for (int s = 0; s < SEQ; s++) {
        const int cur = s & 1;
        const int nxt = cur ^ 1;

        // prefetch epilogue operands (2-deep L2 chain) under staging + compute
        const int   c0 = __ldg(&tids[cb0 * SEQ + s]);
        const int   c1 = __ldg(&tids[(cb0 + 1) * SEQ + s]);
        const float u0 = __ldg(&g_U[c0 * HID + j0 + jc]);
        const float u1 = __ldg(&g_U[c1 * HID + j0 + jc]);

        // ---- stage h tile: sH[k][bb] = h[b0+bb][k], bypassing L1 (.cg) ----
        {
            const float* hrow = g_h[cur] + (b0 + st_bb) * HID;
            float* shb = sH + st_bb;
            #pragma unroll 4
            for (int it = 0; it < 16; it++) {
                int k = (it * 16 + st_kq8) * 4;
                float4 v = __ldcg((const float4*)(hrow + k));
                shb[(k + 0) * SH_STRIDE] = v.x;
                shb[(k + 1) * SH_STRIDE] = v.y;
                shb[(k + 2) * SH_STRIDE] = v.z;
                shb[(k + 3) * SH_STRIDE] = v.w;
            }
        }
        __syncthreads();

        // ---- packed f32x2 partial GEMM: 8b x 4j per lane, 64 k's ----
        u64 acc[4][4];
        #pragma unroll
        for (int bp = 0; bp < 4; bp++)
            #pragma unroll
            for (int j = 0; j < 4; j++) acc[bp][j] = 0ull;

        const float* hptr = hptr0;
        const float* wptr = wptr0;
        #pragma unroll 4
        for (int kk = 0; kk < 64; kk++) {
            float4 hA = *(const float4*)hptr;
            float4 hB = *(const float4*)(hptr + 4);
            float4 wv = *(const float4*)wptr;
            hptr += 16 * SH_STRIDE;
            wptr += 16 * JT;

            u64 hp[4], wd[4];
            PACK2(hp[0], hA.x, hA.y);  PACK2(hp[1], hA.z, hA.w);
            PACK2(hp[2], hB.x, hB.y);  PACK2(hp[3], hB.z, hB.w);
            PACK2(wd[0], wv.x, wv.x);  PACK2(wd[1], wv.y, wv.y);
            PACK2(wd[2], wv.z, wv.z);  PACK2(wd[3], wv.w, wv.w);

            #pragma unroll
            for (int bp = 0; bp < 4; bp++)
                #pragma unroll
                for (int j = 0; j < 4; j++)
                    FMA2(acc[bp][j], hp[bp], wd[j]);
        }

        // ---- intra-warp reduce over ks (lane bits 3,4), then stash partials ----
        #pragma unroll
        for (int bp = 0; bp < 4; bp++) {
            #pragma unroll
            for (int j = 0; j < 4; j++) {
                float lo = __uint_as_float((unsigned)(acc[bp][j] & 0xffffffffull));
                float hi = __uint_as_float((unsigned)(acc[bp][j] >> 32));
                lo += __shfl_xor_sync(0xffffffffu, lo, 8);
                hi += __shfl_xor_sync(0xffffffffu, hi, 8);
                lo += __shfl_xor_sync(0xffffffffu, lo, 16);
                hi += __shfl_xor_sync(0xffffffffu, hi, 16);
                if (ks == 0) {
                    int g = bhalf * 8 + jg;
                    *(float2*)(sP + (kq * 16 + g) * SP_STRIDE + bp * 8 + j * 2)
                        = make_float2(lo, hi);
                }
            }
        }
        __syncthreads();

        // ---- combine 4 kq partials, add U, tanh, write next h ----
        {
            float slo = 0.f, shi = 0.f;
            #pragma unroll
            for (int q = 0; q < 4; q++) {
                float2 v = *(const float2*)(sP + (q * 16 + cg) * SP_STRIDE + cbase);
                slo += v.x; shi += v.y;
            }
            float hn0 = tanhf(slo + u0);
            float hn1 = tanhf(shi + u1);
            __stcg(&g_h[nxt][cb0 * HID + j0 + jc], hn0);
            __stcg(&g_h[nxt][(cb0 + 1) * HID + j0 + jc], hn1);
        }

        flag_bar(line, tj, tagbase + 2u + (unsigned)s);   // phases 2..513
    }

    // ---- final projection: out[b][c] = h_final[b] . W_proj[c] + b_proj[c] ----
    // After s = 511 the final h is in g_h[0]. CTA covers 16 b x 4 chars.
    if (tid < 64) {
        const int bb = tid >> 2;
        const int cc = tid & 3;
        const int b  = b0 + bb;
        const int ch = tj * 4 + cc;
        const float* hp = g_h[0] + b * HID;
        const float* wp = wproj + ch * HID;
        float acc2 = 0.0f;
        #pragma unroll 4
        for (int k = 0; k < HID; k += 4) {
            float4 hv = __ldcg((const float4*)(hp + k));
            float4 wv = *(const float4*)(wp + k);
            acc2 += hv.x*wv.x + hv.y*wv.y + hv.z*wv.z + hv.w*wv.w;
        }
        out[b * NCHAR + ch] = acc2 + bproj[ch];
    }

    flag_bar(line, tj, tagbase + 514u);                  // final phase
}

// ---------------------------------------------------------------------------
// Launch: graph-capturable, no allocations, no syncs.
// Inputs: t, embeddings, W_ih, W_hh, h0, W_proj, b_proj.
// ---------------------------------------------------------------------------
extern "C" void kernel_launch(void* const* d_in, const int* in_sizes, int n_in,
                              void* d_out, int out_size)
{
    const int*   t     = (const int*)  d_in[0];
    const float* emb   = (const float*)d_in[1];
    const float* wih   = (const float*)d_in[2];
    const float* whh   = (const float*)d_in[3];
    const float* h0    = (const float*)d_in[4];
    const float* wproj = (const float*)d_in[5];
    const float* bproj = (const float*)d_in[6];
    float*       out   = (float*)d_out;

    cudaFuncSetAttribute(rnn_kernel, cudaFuncAttributeMaxDynamicSharedMemorySize, SMEM_BYTES);

    u_kernel<<<512, 256>>>(emb, wih);
    rnn_kernel<<<GRID, NTHREADS, SMEM_BYTES>>>(t, whh, h0, wproj, bproj, out);
}

// round 13
// speedup vs baseline: 2.1560x; 2.1560x over previous
#include <cuda_runtime.h>
#include <math.h>

// Problem constants
#define BATCH 64
#define SEQ   512
#define HID   1024
#define EMB   256
#define NCHAR 128

// Geometry (R6 winner): 128 persistent CTAs = 4 batch-groups (tb) x 32 j-tiles (tj).
// 256 threads = 8 warps.
#define GRID     128
#define NTHREADS 256
#define BT       16      // batch rows per CTA
#define JT       32      // hidden rows per CTA

#define SH_STRIDE 20     // padded h-tile row stride (words)
#define SP_STRIDE 34     // partial row stride (words)

#define SW_FLOATS (HID * JT)                    // 32768
#define SH_FLOATS (HID * SH_STRIDE)             // 20480
#define SP_FLOATS (4 * 16 * SP_STRIDE)          // 2176
#define SMEM_FLOATS (SW_FLOATS + SH_FLOATS + SP_FLOATS)
#define SMEM_BYTES  (SMEM_FLOATS * 4)           // 221,696 B

typedef unsigned long long u64;

// packed f32x2 (sm_100+): one SASS FFMA2 = 2 FMAs
#define FMA2(d, a, b)    asm("fma.rn.f32x2 %0, %1, %2, %0;" : "+l"(d) : "l"(a), "l"(b))
#define PACK2(d, lo, hi) asm("mov.b64 %0, {%1, %2};" : "=l"(d) : "f"(lo), "f"(hi))

// Device-global scratch
__device__ float g_U[NCHAR * HID];          // U = embeddings @ W_ih^T
__device__ float g_h[2][BATCH * HID];       // ping-pong hidden state
__device__ unsigned g_count[4];             // per-tb-group barrier counters (self-reset)
__device__ volatile unsigned g_sense[4];    // per-group sense (ends at 0: 514 phases/launch)

// ---------------------------------------------------------------------------
// 32-CTA group barrier (sense reversal) — exactly the 4110us winner's.
// One polling lane per CTA; minimal L2 contention.
// ---------------------------------------------------------------------------
__device__ __forceinline__ void group_barrier(int grp, unsigned s) {
    __syncthreads();
    if (threadIdx.x == 0) {
        __threadfence();
        if (atomicAdd(&g_count[grp], 1u) == 31u) {
            g_count[grp] = 0;
            __threadfence();
            g_sense[grp] = s;
        } else {
            while (g_sense[grp] != s) { }
            __threadfence();
        }
    }
    __syncthreads();
}

// ---------------------------------------------------------------------------
// Kernel 0: U[c][j] = sum_e emb[c][e] * W_ih[j][e]
// ---------------------------------------------------------------------------
__global__ void u_kernel(const float* __restrict__ emb, const float* __restrict__ wih) {
    int gt   = blockIdx.x * blockDim.x + threadIdx.x;
    int warp = gt >> 5;
    int lane = gt & 31;
    int e0   = lane * 8;
    for (int i = 0; i < 32; i++) {
        int o = warp * 32 + i;
        int c = o >> 10;
        int j = o & 1023;
        const float4* ep = (const float4*)(emb + c * EMB + e0);
        const float4* wp = (const float4*)(wih + j * EMB + e0);
        float4 e1 = __ldg(ep),     e2 = __ldg(ep + 1);
        float4 w1 = __ldg(wp),     w2 = __ldg(wp + 1);
        float acc = e1.x*w1.x + e1.y*w1.y + e1.z*w1.z + e1.w*w1.w
                  + e2.x*w2.x + e2.y*w2.y + e2.z*w2.z + e2.w*w2.w;
        acc += __shfl_xor_sync(0xffffffffu, acc, 16);
        acc += __shfl_xor_sync(0xffffffffu, acc, 8);
        acc += __shfl_xor_sync(0xffffffffu, acc, 4);
        acc += __shfl_xor_sync(0xffffffffu, acc, 2);
        acc += __shfl_xor_sync(0xffffffffu, acc, 1);
        if (lane == 0) g_U[c * HID + j] = acc;
    }
}

// ---------------------------------------------------------------------------
// Persistent RNN scan — the 4110us kernel with ONE delta: the epilogue's
// t[b,s] -> U[c,:] 2-deep L2 chain is prefetched at the top of the step
// (hidden under staging + GEMM) instead of resolved inside the combine.
// ---------------------------------------------------------------------------
__global__ void __launch_bounds__(NTHREADS, 1) rnn_kernel(
    const int*   __restrict__ tids,
    const float* __restrict__ whh,
    const float* __restrict__ h0,
    const float* __restrict__ wproj,
    const float* __restrict__ bproj,
    float*       __restrict__ out)
{
    extern __shared__ float smem[];
    float* sW = smem;                         // [1024][32]   W slice, transposed
    float* sH = smem + SW_FLOATS;             // [1024][20]   h tile, transposed, padded
    float* sP = smem + SW_FLOATS + SH_FLOATS; // [4][16][34]  cross-warp partials

    const int tid = threadIdx.x;
    const int cta = blockIdx.x;
    const int tb  = cta >> 5;      // 0..3 (barrier group)
    const int tj  = cta & 31;      // 0..31
    const int b0  = tb * BT;
    const int j0  = tj * JT;

    // one-time: W_hh slice transposed into SMEM
    for (int idx = tid; idx < JT * HID; idx += NTHREADS) {
        int jj = idx >> 10;
        int k  = idx & 1023;
        sW[k * JT + jj] = whh[(j0 + jj) * HID + k];
    }
    // one-time: init h ping buffer (this CTA's tile)
    for (int idx = tid; idx < BT * JT; idx += NTHREADS) {
        int bb = idx >> 5;
        int jj = idx & 31;
        g_h[0][(b0 + bb) * HID + (j0 + jj)] = h0[j0 + jj];
    }

    unsigned bsense = 0;
    bsense ^= 1; group_barrier(tb, bsense);          // barrier #1

    const int w     = tid >> 5;
    const int l     = tid & 31;
    const int bhalf = w & 1;       // 8-batch half
    const int kq    = w >> 1;      // 0..3
    const int jg    = l & 7;       // 4 j's
    const int ks    = l >> 3;      // 0..3
    const int klane = kq * 4 + ks;

    // staging assignment: thread -> (bb, kq8)
    const int st_bb  = tid & 15;
    const int st_kq8 = tid >> 4;   // 0..15

    // combine assignment: thread -> (bpg, jc)
    const int jc  = tid & 31;
    const int bpg = tid >> 5;      // 0..7
    const int cbh = bpg >> 2;
    const int cbp = bpg & 3;
    const int cg  = cbh * 8 + (jc >> 2);
    const int cbase = cbp * 8 + (jc & 3) * 2;
    const int cb0 = b0 + cbh * 8 + cbp * 2;

    for (int s = 0; s < SEQ; s++) {
        const int cur = s & 1;
        const int nxt = cur ^ 1;

        // DELTA: prefetch epilogue operands (2-deep L2 chain) under staging+GEMM
        const int   c0 = __ldg(&tids[cb0 * SEQ + s]);
        const int   c1 = __ldg(&tids[(cb0 + 1) * SEQ + s]);
        const float u0 = __ldg(&g_U[c0 * HID + j0 + jc]);
        const float u1 = __ldg(&g_U[c1 * HID + j0 + jc]);

        // ---- stage h tile: sH[k][bb] = h[b0+bb][k], bypassing L1 (.cg) ----
        {
            const float* hrow = g_h[cur] + (b0 + st_bb) * HID;
            float* shb = sH + st_bb;
            #pragma unroll 4
            for (int it = 0; it < 16; it++) {
                int k = (it * 16 + st_kq8) * 4;
                float4 v = __ldcg((const float4*)(hrow + k));
                shb[(k + 0) * SH_STRIDE] = v.x;
                shb[(k + 1) * SH_STRIDE] = v.y;
                shb[(k + 2) * SH_STRIDE] = v.z;
                shb[(k + 3) * SH_STRIDE] = v.w;
            }
        }
        __syncthreads();

        // ---- packed f32x2 partial GEMM: 8b x 4j per lane, 64 k's ----
        u64 acc[4][4];
        #pragma unroll
        for (int bp = 0; bp < 4; bp++)
            #pragma unroll
            for (int j = 0; j < 4; j++) acc[bp][j] = 0ull;

        const float* hptr = sH + klane * SH_STRIDE + bhalf * 8;
        const float* wptr = sW + klane * JT + jg * 4;

        #pragma unroll 4
        for (int kk = 0; kk < 64; kk++) {
            float4 hA = *(const float4*)hptr;
            float4 hB = *(const float4*)(hptr + 4);
            float4 wv = *(const float4*)wptr;
            hptr += 16 * SH_STRIDE;
            wptr += 16 * JT;

            u64 hp[4], wd[4];
            PACK2(hp[0], hA.x, hA.y);  PACK2(hp[1], hA.z, hA.w);
            PACK2(hp[2], hB.x, hB.y);  PACK2(hp[3], hB.z, hB.w);
            PACK2(wd[0], wv.x, wv.x);  PACK2(wd[1], wv.y, wv.y);
            PACK2(wd[2], wv.z, wv.z);  PACK2(wd[3], wv.w, wv.w);

            #pragma unroll
            for (int bp = 0; bp < 4; bp++)
                #pragma unroll
                for (int j = 0; j < 4; j++)
                    FMA2(acc[bp][j], hp[bp], wd[j]);
        }

        // ---- intra-warp reduce over ks (lane bits 3,4), then stash partials ----
        #pragma unroll
        for (int bp = 0; bp < 4; bp++) {
            #pragma unroll
            for (int j = 0; j < 4; j++) {
                float lo = __uint_as_float((unsigned)(acc[bp][j] & 0xffffffffull));
                float hi = __uint_as_float((unsigned)(acc[bp][j] >> 32));
                lo += __shfl_xor_sync(0xffffffffu, lo, 8);
                hi += __shfl_xor_sync(0xffffffffu, hi, 8);
                lo += __shfl_xor_sync(0xffffffffu, lo, 16);
                hi += __shfl_xor_sync(0xffffffffu, hi, 16);
                if (ks == 0) {
                    int g = bhalf * 8 + jg;
                    *(float2*)(sP + (kq * 16 + g) * SP_STRIDE + bp * 8 + j * 2)
                        = make_float2(lo, hi);
                }
            }
        }
        __syncthreads();

        // ---- combine 4 kq partials, add U (prefetched), tanh, write next h ----
        {
            float slo = 0.f, shi = 0.f;
            #pragma unroll
            for (int q = 0; q < 4; q++) {
                float2 v = *(const float2*)(sP + (q * 16 + cg) * SP_STRIDE + cbase);
                slo += v.x; shi += v.y;
            }
            float hn0 = tanhf(slo + u0);
            float hn1 = tanhf(shi + u1);
            __stcg(&g_h[nxt][cb0 * HID + j0 + jc], hn0);
            __stcg(&g_h[nxt][(cb0 + 1) * HID + j0 + jc], hn1);
        }

        bsense ^= 1; group_barrier(tb, bsense);      // barriers #2..#513
    }

    // ---- final projection: out[b][c] = h_final[b] . W_proj[c] + b_proj[c] ----
    // After s = 511 the final h is in g_h[0]. CTA covers 16 b x 4 chars.
    if (tid < 64) {
        const int bb = tid >> 2;
        const int cc = tid & 3;
        const int b  = b0 + bb;
        const int c  = tj * 4 + cc;
        const float* hp = g_h[0] + b * HID;
        const float* wp = wproj + c * HID;
        float acc2 = 0.0f;
        #pragma unroll 4
        for (int k = 0; k < HID; k += 4) {
            float4 hv = __ldcg((const float4*)(hp + k));
            float4 wv = *(const float4*)(wp + k);
            acc2 += hv.x*wv.x + hv.y*wv.y + hv.z*wv.z + hv.w*wv.w;
        }
        out[b * NCHAR + c] = acc2 + bproj[c];
    }

    bsense ^= 1; group_barrier(tb, bsense);          // barrier #514 (sense -> 0)
}

// ---------------------------------------------------------------------------
// Launch: graph-capturable, no allocations, no syncs.
// Inputs: t, embeddings, W_ih, W_hh, h0, W_proj, b_proj.
// ---------------------------------------------------------------------------
extern "C" void kernel_launch(void* const* d_in, const int* in_sizes, int n_in,
                              void* d_out, int out_size)
{
    const int*   t     = (const int*)  d_in[0];
    const float* emb   = (const float*)d_in[1];
    const float* wih   = (const float*)d_in[2];
    const float* whh   = (const float*)d_in[3];
    const float* h0    = (const float*)d_in[4];
    const float* wproj = (const float*)d_in[5];
    const float* bproj = (const float*)d_in[6];
    float*       out   = (float*)d_out;

    cudaFuncSetAttribute(rnn_kernel, cudaFuncAttributeMaxDynamicSharedMemorySize, SMEM_BYTES);

    u_kernel<<<512, 256>>>(emb, wih);
    rnn_kernel<<<GRID, NTHREADS, SMEM_BYTES>>>(t, whh, h0, wproj, bproj, out);
}